// round 3
// baseline (speedup 1.0000x reference)
#include <cuda_runtime.h>
#include <cstdint>

// CoCov: sum over 9 tile-shifts of per-16x16-tile zero-padded 3x3 convs, 64->64 ch.
// FFMA2 (packed fp32x2) version: each thread accumulates 8 pixels x 4 channel-pairs.

#define NTOT (9*64*64*9)

// weights transposed to [ci][k][tap][co] for coalesced per-ci staging
__device__ float g_wt[64 * 9 * 9 * 64];

__global__ void transpose_weights_kernel(const float* __restrict__ K) {
    int idx = blockIdx.x * blockDim.x + threadIdx.x;
    if (idx >= NTOT) return;
    // source layout: [k][co][ci][dh][dw], idx = ((k*64+co)*64+ci)*9 + tap
    int tap = idx % 9;
    int t = idx / 9;
    int ci = t & 63; t >>= 6;
    int co = t & 63; t >>= 6;
    int k = t;
    g_wt[((ci * 9 + k) * 9 + tap) * 64 + co] = K[idx];
}

__device__ __forceinline__ void ffma2(unsigned long long& acc,
                                      unsigned long long x,
                                      unsigned long long w) {
    asm("fma.rn.f32x2 %0, %1, %2, %0;" : "+l"(acc) : "l"(x), "l"(w));
}

__global__ __launch_bounds__(256, 2)
void cocov_kernel(const float* __restrict__ inp, float* __restrict__ out) {
    // 9 input tiles, 18x18 zero-bordered frames, each value DUPLICATED (float2)
    // so ld.shared.b64 yields a packed broadcast operand for fma.rn.f32x2.
    __shared__ __align__(16) float2 s_in[9][18][18];
    // weights for current ci: [k][tap][co]
    __shared__ __align__(16) float s_w[9 * 9 * 64];

    const int t2 = blockIdx.x;      // tile col
    const int t1 = blockIdx.y;      // tile row
    const int b  = blockIdx.z;      // batch
    const int tid  = threadIdx.x;
    const int lane = tid & 31;
    const int wid  = tid >> 5;
    const int cobase = wid << 3;          // each warp: 8 output channels
    const int i0 = (lane >> 4);           // 0/1 : pixel row parity within pair
    const int j  = lane & 15;             // pixel col

    // zero the padded input frames once; interiors rewritten every ci,
    // borders stay zero for the whole kernel.
    {
        float2* f = &s_in[0][0][0];
        for (int e = tid; e < 9 * 18 * 18; e += 256) f[e] = make_float2(0.f, 0.f);
    }

    // loader mapping: thread -> (row ii, col jj) of a 16x16 tile
    const int ii = tid >> 4;
    const int jj = tid & 15;

    // per-tile global base offsets + validity mask
    int base[9];
    unsigned vmask = 0;
    #pragma unroll
    for (int kt = 0; kt < 9; kt++) {
        int r = kt / 3, c = kt % 3;
        int tt1 = t1 + r - 1, tt2 = t2 + c - 1;
        if (tt1 >= 0 && tt1 < 16 && tt2 >= 0 && tt2 < 16) vmask |= (1u << kt);
        base[kt] = ((b * 64) * 256 + tt1 * 16 + ii) * 256 + tt2 * 16 + jj;
    }

    // 8 pixels (rows 2q+i0, col j) x 4 packed channel-pairs per thread
    unsigned long long acc[8][4];
    #pragma unroll
    for (int q = 0; q < 8; q++)
        #pragma unroll
        for (int p = 0; p < 4; p++) acc[q][p] = 0ull;

    for (int ci = 0; ci < 64; ci++) {
        __syncthreads();

        // stage 9 input tiles for this ci (duplicated values)
        const int cioff = ci * 256 * 256;
        #pragma unroll
        for (int kt = 0; kt < 9; kt++) {
            float v = ((vmask >> kt) & 1) ? __ldg(inp + base[kt] + cioff) : 0.f;
            s_in[kt][ii + 1][jj + 1] = make_float2(v, v);
        }

        // stage weights for this ci (coalesced float4)
        {
            const float4* ws4 = (const float4*)(g_wt + ci * (9 * 9 * 64));
            float4* sw4 = (float4*)s_w;
            for (int e = tid; e < (9 * 9 * 64) / 4; e += 256) sw4[e] = ws4[e];
        }
        __syncthreads();

        #pragma unroll 1
        for (int kt = 0; kt < 9; kt++) {
            const float2* tin = &s_in[kt][0][0];
            const float* tw  = &s_w[kt * 576 + cobase];
            #pragma unroll
            for (int tap = 0; tap < 9; tap++) {
                const int dh = tap / 3, dw = tap % 3;
                // packed weight pairs straight from smem (LDS.128 x2)
                ulonglong2 wa = *(const ulonglong2*)(tw + tap * 64);
                ulonglong2 wb = *(const ulonglong2*)(tw + tap * 64 + 4);
                unsigned long long x[8];
                #pragma unroll
                for (int q = 0; q < 8; q++)
                    x[q] = *(const unsigned long long*)
                               (tin + (2 * q + i0 + dh) * 18 + (j + dw));
                #pragma unroll
                for (int q = 0; q < 8; q++) {
                    ffma2(acc[q][0], x[q], wa.x);
                    ffma2(acc[q][1], x[q], wa.y);
                    ffma2(acc[q][2], x[q], wb.x);
                    ffma2(acc[q][3], x[q], wb.y);
                }
            }
        }
    }

    // epilogue: out[b, cobase+2p(+0/1), t1*16 + 2q+i0, t2*16 + j]
    const size_t obase =
        ((size_t)(b * 64 + cobase) * 256 + (size_t)(t1 * 16 + i0)) * 256 + t2 * 16 + j;
    #pragma unroll
    for (int p = 0; p < 4; p++) {
        #pragma unroll
        for (int q = 0; q < 8; q++) {
            unsigned long long a = acc[q][p];
            float lo = __uint_as_float((unsigned)(a & 0xffffffffull));
            float hi = __uint_as_float((unsigned)(a >> 32));
            size_t o = obase + (size_t)(2 * p) * 65536 + (size_t)q * 512;
            out[o]          = lo;
            out[o + 65536]  = hi;
        }
    }
}

extern "C" void kernel_launch(void* const* d_in, const int* in_sizes, int n_in,
                              void* d_out, int out_size) {
    const float* inp = (const float*)d_in[0];   // (8, 64, 256, 256) fp32
    const float* ker = (const float*)d_in[1];   // (9, 64, 64, 3, 3) fp32
    float* out = (float*)d_out;                 // (8, 64, 256, 256) fp32

    transpose_weights_kernel<<<(NTOT + 255) / 256, 256>>>(ker);

    dim3 grid(16, 16, 8);   // (t2, t1, b)
    cocov_kernel<<<grid, 256>>>(inp, out);
}

// round 4
// speedup vs baseline: 1.7641x; 1.7641x over previous
#include <cuda_runtime.h>
#include <cuda_bf16.h>
#include <cstdint>

// ============================================================================
// CoCov via legacy mma.sync (HMMA) bf16x3:
// out tile = sum_{kt 3x3} sum_{tap 3x3} shift_tap( X_kt[256,64] @ W[kt,tap][64,64] )
// 3 precision passes (hi*hi + lo*hi + hi*lo) in fp32 accumulators.
// ============================================================================

// pre-split weights: [kt*9+tap][prec hi/lo][ci 64][co 64] bf16
__device__ __nv_bfloat16 g_bw[81 * 2 * 64 * 64];

__global__ void wtrans_kernel(const float* __restrict__ K) {
    int gid = blockIdx.x * blockDim.x + threadIdx.x;
    if (gid >= 9 * 9 * 64 * 64) return;
    int co = gid & 63;
    int ci = (gid >> 6) & 63;
    int tp = (gid >> 12) % 9;
    int kt = (gid >> 12) / 9;
    float w = K[(((kt * 64 + co) * 64 + ci) * 9) + tp];   // [k][co][ci][dh][dw]
    __nv_bfloat16 hi = __float2bfloat16(w);
    __nv_bfloat16 lo = __float2bfloat16(w - __bfloat162float(hi));
    size_t base = (size_t)(kt * 9 + tp) * 8192 + ci * 64 + co;
    g_bw[base]        = hi;
    g_bw[base + 4096] = lo;
}

__device__ __forceinline__ uint32_t smem_u32(const void* p) {
    uint32_t a;
    asm("{ .reg .u64 t; cvta.to.shared.u64 t, %1; cvt.u32.u64 %0, t; }" : "=r"(a) : "l"(p));
    return a;
}

__device__ __forceinline__ void ldsm_x4(uint32_t* r, uint32_t addr) {
    asm volatile("ldmatrix.sync.aligned.m8n8.x4.shared.b16 {%0,%1,%2,%3}, [%4];"
                 : "=r"(r[0]), "=r"(r[1]), "=r"(r[2]), "=r"(r[3]) : "r"(addr));
}
__device__ __forceinline__ void ldsm_x4_t(uint32_t* r, uint32_t addr) {
    asm volatile("ldmatrix.sync.aligned.m8n8.x4.trans.shared.b16 {%0,%1,%2,%3}, [%4];"
                 : "=r"(r[0]), "=r"(r[1]), "=r"(r[2]), "=r"(r[3]) : "r"(addr));
}
__device__ __forceinline__ void mma16816(float* d, const uint32_t* a, const uint32_t* b) {
    asm volatile(
        "mma.sync.aligned.m16n8k16.row.col.f32.bf16.bf16.f32 "
        "{%0,%1,%2,%3}, {%4,%5,%6,%7}, {%8,%9}, {%0,%1,%2,%3};"
        : "+f"(d[0]), "+f"(d[1]), "+f"(d[2]), "+f"(d[3])
        : "r"(a[0]), "r"(a[1]), "r"(a[2]), "r"(a[3]), "r"(b[0]), "r"(b[1]));
}

// smem layout (bytes):
//   [0]      A: [prec 2][pix 256][ci 64] bf16, 128B rows, XOR-swizzled  = 64 KB
//   [65536]  B: [prec 2][ci 64][co 64]  bf16, 128B rows, XOR-swizzled   = 16 KB
//   [81920]  acc: [pix 256][72 pad] fp32                                = 72 KB
#define SM_A   0
#define SM_B   65536
#define SM_ACC 81920
#define SM_TOTAL (81920 + 256 * 72 * 4)

__global__ void __launch_bounds__(256, 1)
cocov_mma_kernel(const float* __restrict__ inp, float* __restrict__ out) {
    extern __shared__ char smem[];
    const uint32_t sb = smem_u32(smem);
    const uint32_t aA = sb + SM_A;
    const uint32_t aB = sb + SM_B;
    float* accS = (float*)(smem + SM_ACC);

    const int tid = threadIdx.x;
    const int lane = tid & 31;
    const int wid = tid >> 5;
    const int t2 = blockIdx.x, t1 = blockIdx.y, b = blockIdx.z;

    // zero pixel-domain accumulator
    for (int e = tid; e < 256 * 72; e += 256) accS[e] = 0.f;

    // precomputed ldmatrix lane addressing pieces
    const int M0 = wid * 32;
    const int a_row_base = M0 + (lane & 15);             // + mt*16
    const int a_kc_lane  = (lane >> 4);                  // + k16*2
    const int b_row_lane = (lane & 7) + ((lane >> 3) & 1) * 8;  // + k16*16
    const int b_nc_lane  = (lane >> 4);                  // + 2*g

    const uint4* wsrc_all = (const uint4*)g_bw;

    for (int kt = 0; kt < 9; kt++) {
        // ---- stage A(kt): pixel=tid, 64 ci, bf16 hi/lo, swizzled 128B rows ----
        {
            const int tt1 = t1 + kt / 3 - 1;
            const int tt2 = t2 + kt % 3 - 1;
            const bool v = ((unsigned)tt1 < 16u) && ((unsigned)tt2 < 16u);
            const float* src = inp + (size_t)b * 64 * 65536
                + (v ? (size_t)(tt1 * 16 + (tid >> 4)) * 256 + tt2 * 16 + (tid & 15) : 0);
            const uint32_t rowa = aA + tid * 128;
            #pragma unroll
            for (int ch = 0; ch < 8; ch++) {
                uint32_t hi4[4], lo4[4];
                #pragma unroll
                for (int e = 0; e < 4; e++) {
                    float x0 = v ? __ldg(src + (size_t)(ch * 8 + 2 * e) * 65536) : 0.f;
                    float x1 = v ? __ldg(src + (size_t)(ch * 8 + 2 * e + 1) * 65536) : 0.f;
                    __nv_bfloat16 h0 = __float2bfloat16(x0);
                    __nv_bfloat16 h1 = __float2bfloat16(x1);
                    __nv_bfloat16 l0 = __float2bfloat16(x0 - __bfloat162float(h0));
                    __nv_bfloat16 l1 = __float2bfloat16(x1 - __bfloat162float(h1));
                    __nv_bfloat162 hp(h0, h1), lp(l0, l1);
                    hi4[e] = *(uint32_t*)&hp;
                    lo4[e] = *(uint32_t*)&lp;
                }
                uint32_t off = rowa + ((ch ^ (tid & 7)) << 4);
                asm volatile("st.shared.v4.b32 [%0], {%1,%2,%3,%4};"
                             :: "r"(off), "r"(hi4[0]), "r"(hi4[1]), "r"(hi4[2]), "r"(hi4[3]));
                asm volatile("st.shared.v4.b32 [%0], {%1,%2,%3,%4};"
                             :: "r"(off + 32768), "r"(lo4[0]), "r"(lo4[1]), "r"(lo4[2]), "r"(lo4[3]));
            }
        }

        for (int tp = 0; tp < 9; tp++) {
            // ---- stage B(kt,tp): 16KB, swizzled ----
            {
                const uint4* wsrc = wsrc_all + (size_t)(kt * 9 + tp) * 1024;
                #pragma unroll
                for (int it = 0; it < 4; it++) {
                    int c = tid + it * 256;
                    int prec = c >> 9, ci = (c >> 3) & 63, coch = c & 7;
                    uint4 wv = __ldg(wsrc + c);
                    uint32_t off = aB + prec * 8192 + ci * 128 + ((coch ^ (ci & 7)) << 4);
                    asm volatile("st.shared.v4.b32 [%0], {%1,%2,%3,%4};"
                                 :: "r"(off), "r"(wv.x), "r"(wv.y), "r"(wv.z), "r"(wv.w));
                }
            }
            __syncthreads();

            // ---- GEMM: 32 pix x 64 co x (64 ci x 3 passes) per warp ----
            float d[2][8][4];
            #pragma unroll
            for (int mt = 0; mt < 2; mt++)
                #pragma unroll
                for (int nt = 0; nt < 8; nt++)
                    #pragma unroll
                    for (int r = 0; r < 4; r++) d[mt][nt][r] = 0.f;

            #pragma unroll
            for (int pass = 0; pass < 3; pass++) {
                const uint32_t pAoff = (pass == 1) ? 32768u : 0u;
                const uint32_t pBoff = (pass == 2) ? 8192u : 0u;
                #pragma unroll
                for (int k16 = 0; k16 < 4; k16++) {
                    uint32_t a[2][4];
                    #pragma unroll
                    for (int mt = 0; mt < 2; mt++) {
                        int row = a_row_base + mt * 16;
                        int kc = k16 * 2 + a_kc_lane;
                        ldsm_x4(a[mt], aA + pAoff + row * 128 + ((kc ^ (row & 7)) << 4));
                    }
                    uint32_t bf[8][2];
                    #pragma unroll
                    for (int g = 0; g < 4; g++) {
                        int brow = k16 * 16 + b_row_lane;
                        int bnc = 2 * g + b_nc_lane;
                        uint32_t rr[4];
                        ldsm_x4_t(rr, aB + pBoff + brow * 128 + ((bnc ^ (brow & 7)) << 4));
                        bf[2 * g][0] = rr[0]; bf[2 * g][1] = rr[1];
                        bf[2 * g + 1][0] = rr[2]; bf[2 * g + 1][1] = rr[3];
                    }
                    #pragma unroll
                    for (int mt = 0; mt < 2; mt++)
                        #pragma unroll
                        for (int nt = 0; nt < 8; nt++)
                            mma16816(d[mt][nt], a[mt], bf[nt]);
                }
            }

            // ---- scatter-add with tap shift (uniform shift -> no warp races) ----
            const int di = 1 - tp / 3;
            const int dj = 1 - tp % 3;
            #pragma unroll
            for (int mt = 0; mt < 2; mt++) {
                const int prow = M0 + mt * 16 + (lane >> 2);
                #pragma unroll
                for (int r = 0; r < 4; r++) {
                    const int p = prow + ((r >> 1) & 1) * 8;
                    const int o1 = (p >> 4) + di;
                    const int o2 = (p & 15) + dj;
                    if (((unsigned)o1 < 16u) && ((unsigned)o2 < 16u)) {
                        float* dst = accS + (o1 * 16 + o2) * 72 + (lane & 3) * 2 + (r & 1);
                        #pragma unroll
                        for (int nt = 0; nt < 8; nt++)
                            dst[nt * 8] += d[mt][nt][r];
                    }
                }
            }
            __syncthreads();
        }
    }

    // ---- epilogue: acc -> global ----
    {
        const size_t obase = ((size_t)(b * 64) * 256 + (size_t)(t1 * 16 + (tid >> 4))) * 256
                             + t2 * 16 + (tid & 15);
        const float* arow = accS + tid * 72;
        #pragma unroll 8
        for (int co = 0; co < 64; co++)
            out[obase + (size_t)co * 65536] = arow[co];
    }
}

extern "C" void kernel_launch(void* const* d_in, const int* in_sizes, int n_in,
                              void* d_out, int out_size) {
    const float* inp = (const float*)d_in[0];   // (8, 64, 256, 256) fp32
    const float* ker = (const float*)d_in[1];   // (9, 64, 64, 3, 3) fp32
    float* out = (float*)d_out;                 // (8, 64, 256, 256) fp32

    wtrans_kernel<<<(9 * 9 * 64 * 64 + 255) / 256, 256>>>(ker);

    cudaFuncSetAttribute(cocov_mma_kernel,
                         cudaFuncAttributeMaxDynamicSharedMemorySize, SM_TOTAL);
    dim3 grid(16, 16, 8);   // (t2, t1, b)
    cocov_mma_kernel<<<grid, 256, SM_TOTAL>>>(inp, out);
}

// round 5
// speedup vs baseline: 2.7900x; 1.5815x over previous
#include <cuda_runtime.h>
#include <cuda_bf16.h>
#include <cstdint>

// ============================================================================
// CoCov via mma.sync (HMMA) bf16x3, input-shift formulation:
// out[p] = sum_{kt 3x3} sum_{tap 3x3} X_kt[p + (dh-1,dw-1)] @ W[kt,tap]
// Output fragments live in registers across all 81 (kt,tap) combos; the tap
// shift is applied through ldmatrix per-lane row addresses (zero row for
// out-of-tile pixels). 3 precision passes (hi*hi + lo*hi + hi*lo), fp32 acc.
// ============================================================================

// pre-split weights: [kt*9+tap][prec hi/lo][ci 64][co 64] bf16
__device__ __nv_bfloat16 g_bw[81 * 2 * 64 * 64];

__global__ void wtrans_kernel(const float* __restrict__ K) {
    int gid = blockIdx.x * blockDim.x + threadIdx.x;
    if (gid >= 9 * 9 * 64 * 64) return;
    int co = gid & 63;
    int ci = (gid >> 6) & 63;
    int tp = (gid >> 12) % 9;
    int kt = (gid >> 12) / 9;
    float w = K[(((kt * 64 + co) * 64 + ci) * 9) + tp];   // [k][co][ci][dh][dw]
    __nv_bfloat16 hi = __float2bfloat16(w);
    __nv_bfloat16 lo = __float2bfloat16(w - __bfloat162float(hi));
    size_t base = (size_t)(kt * 9 + tp) * 8192 + ci * 64 + co;
    g_bw[base]        = hi;
    g_bw[base + 4096] = lo;
}

__device__ __forceinline__ uint32_t smem_u32(const void* p) {
    uint32_t a;
    asm("{ .reg .u64 t; cvta.to.shared.u64 t, %1; cvt.u32.u64 %0, t; }" : "=r"(a) : "l"(p));
    return a;
}
__device__ __forceinline__ void ldsm_x4(uint32_t* r, uint32_t addr) {
    asm volatile("ldmatrix.sync.aligned.m8n8.x4.shared.b16 {%0,%1,%2,%3}, [%4];"
                 : "=r"(r[0]), "=r"(r[1]), "=r"(r[2]), "=r"(r[3]) : "r"(addr));
}
__device__ __forceinline__ void ldsm_x4_t(uint32_t* r, uint32_t addr) {
    asm volatile("ldmatrix.sync.aligned.m8n8.x4.trans.shared.b16 {%0,%1,%2,%3}, [%4];"
                 : "=r"(r[0]), "=r"(r[1]), "=r"(r[2]), "=r"(r[3]) : "r"(addr));
}
__device__ __forceinline__ void mma16816(float* d, const uint32_t* a, const uint32_t* b) {
    asm volatile(
        "mma.sync.aligned.m16n8k16.row.col.f32.bf16.bf16.f32 "
        "{%0,%1,%2,%3}, {%4,%5,%6,%7}, {%8,%9}, {%0,%1,%2,%3};"
        : "+f"(d[0]), "+f"(d[1]), "+f"(d[2]), "+f"(d[3])
        : "r"(a[0]), "r"(a[1]), "r"(a[2]), "r"(a[3]), "r"(b[0]), "r"(b[1]));
}

// smem layout (bytes):
//   [0]      A: [prec 2][257 rows][128B]  (row 256 = zeros)   = 65792
//   [66560]  B: [tap 9][prec 2][ci 64][128B]                  = 147456
//   epilogue reuses B region as acc [pix 256][72] fp32        = 73728
#define A_PLANE  32896          // 257 * 128
#define SM_A     0
#define SM_B     66560
#define SM_TOTAL (66560 + 147456)

__global__ void __launch_bounds__(256, 1)
cocov_mma_kernel(const float* __restrict__ inp, float* __restrict__ out) {
    extern __shared__ char smem[];
    const uint32_t sb = smem_u32(smem);
    const uint32_t aA = sb + SM_A;
    const uint32_t aB = sb + SM_B;

    const int tid = threadIdx.x;
    const int lane = tid & 31;
    const int wid = tid >> 5;
    const int t2 = blockIdx.x, t1 = blockIdx.y, b = blockIdx.z;
    const int M0 = wid * 32;

    // zero rows (row 256 of each precision plane), written once
    if (tid < 64) {
        int pl = tid >> 5;
        *(float*)(smem + SM_A + pl * A_PLANE + 256 * 128 + (tid & 31) * 4) = 0.f;
    }

    // ldmatrix lane addressing pieces
    const int a_kc_lane  = (lane >> 4);                          // A: + k16*2
    const int b_row_lane = (lane & 7) + ((lane >> 3) & 1) * 8;   // B: + k16*16
    const int b_nc_lane  = (lane >> 4);                          // B: + 2*g
    const int jlane      = lane & 15;                            // A pixel col

    // output fragments: 32 pixels x 64 co per warp, held across all 81 combos
    float d[2][8][4];
    #pragma unroll
    for (int mt = 0; mt < 2; mt++)
        #pragma unroll
        for (int nt = 0; nt < 8; nt++)
            #pragma unroll
            for (int r = 0; r < 4; r++) d[mt][nt][r] = 0.f;

    const uint4* wsrc_all = (const uint4*)g_bw;

    for (int kt = 0; kt < 9; kt++) {
        __syncthreads();   // previous kt's ldsm reads complete (and zero-row init)

        // ---- stage A(kt): pixel=tid, 64 ci, bf16 hi/lo, swizzled 128B rows ----
        {
            const int tt1 = t1 + kt / 3 - 1;
            const int tt2 = t2 + kt % 3 - 1;
            const bool v = ((unsigned)tt1 < 16u) && ((unsigned)tt2 < 16u);
            const float* src = inp + (size_t)b * 64 * 65536
                + (v ? (size_t)(tt1 * 16 + (tid >> 4)) * 256 + tt2 * 16 + (tid & 15) : 0);
            const uint32_t rowa = aA + tid * 128;
            #pragma unroll
            for (int ch = 0; ch < 8; ch++) {
                uint32_t hi4[4], lo4[4];
                #pragma unroll
                for (int e = 0; e < 4; e++) {
                    float x0 = v ? __ldg(src + (size_t)(ch * 8 + 2 * e) * 65536) : 0.f;
                    float x1 = v ? __ldg(src + (size_t)(ch * 8 + 2 * e + 1) * 65536) : 0.f;
                    __nv_bfloat16 h0 = __float2bfloat16(x0);
                    __nv_bfloat16 h1 = __float2bfloat16(x1);
                    __nv_bfloat16 l0 = __float2bfloat16(x0 - __bfloat162float(h0));
                    __nv_bfloat16 l1 = __float2bfloat16(x1 - __bfloat162float(h1));
                    __nv_bfloat162 hp(h0, h1), lp(l0, l1);
                    hi4[e] = *(uint32_t*)&hp;
                    lo4[e] = *(uint32_t*)&lp;
                }
                uint32_t off = rowa + ((ch ^ (tid & 7)) << 4);
                asm volatile("st.shared.v4.b32 [%0], {%1,%2,%3,%4};"
                             :: "r"(off), "r"(hi4[0]), "r"(hi4[1]), "r"(hi4[2]), "r"(hi4[3]));
                asm volatile("st.shared.v4.b32 [%0], {%1,%2,%3,%4};"
                             :: "r"(off + A_PLANE), "r"(lo4[0]), "r"(lo4[1]), "r"(lo4[2]), "r"(lo4[3]));
            }
        }

        // ---- stage all 9 taps' B for this kt: 144KB ----
        {
            const uint4* wsrc = wsrc_all + (size_t)kt * 9216;
            #pragma unroll
            for (int it = 0; it < 36; it++) {
                int c = tid + it * 256;                 // 0..9215
                int tp   = c >> 10;
                int prec = (c >> 9) & 1;
                int ci   = (c >> 3) & 63;
                int coch = c & 7;
                uint4 wv = __ldg(wsrc + c);
                uint32_t off = aB + tp * 16384 + prec * 8192 + ci * 128
                             + ((coch ^ (ci & 7)) << 4);
                asm volatile("st.shared.v4.b32 [%0], {%1,%2,%3,%4};"
                             :: "r"(off), "r"(wv.x), "r"(wv.y), "r"(wv.z), "r"(wv.w));
            }
        }
        __syncthreads();

        #pragma unroll 1
        for (int tp = 0; tp < 9; tp++) {
            // shifted A row addresses for this tap (zero row 256 when invalid)
            const int dh = tp / 3 - 1, dw = tp % 3 - 1;
            const int sj = jlane + dw;
            const bool jv = (unsigned)sj < 16u;
            uint32_t rowbase[2];
            int key[2];
            #pragma unroll
            for (int mt = 0; mt < 2; mt++) {
                int si = wid * 2 + mt + dh;
                int srow = (jv && ((unsigned)si < 16u)) ? si * 16 + sj : 256;
                rowbase[mt] = aA + (uint32_t)srow * 128;
                key[mt] = srow & 7;
            }
            const uint32_t bbase = aB + tp * 16384;

            #pragma unroll
            for (int pass = 0; pass < 3; pass++) {
                const uint32_t pAoff = (pass == 1) ? (uint32_t)A_PLANE : 0u;
                const uint32_t pBoff = (pass == 2) ? 8192u : 0u;
                #pragma unroll
                for (int k16 = 0; k16 < 4; k16++) {
                    const int kc = k16 * 2 + a_kc_lane;
                    uint32_t a[2][4];
                    #pragma unroll
                    for (int mt = 0; mt < 2; mt++)
                        ldsm_x4(a[mt], rowbase[mt] + pAoff + ((kc ^ key[mt]) << 4));
                    uint32_t bf[8][2];
                    const int brow = k16 * 16 + b_row_lane;
                    #pragma unroll
                    for (int g = 0; g < 4; g++) {
                        int bnc = 2 * g + b_nc_lane;
                        uint32_t rr[4];
                        ldsm_x4_t(rr, bbase + pBoff + brow * 128
                                      + ((bnc ^ (brow & 7)) << 4));
                        bf[2 * g][0] = rr[0]; bf[2 * g][1] = rr[1];
                        bf[2 * g + 1][0] = rr[2]; bf[2 * g + 1][1] = rr[3];
                    }
                    #pragma unroll
                    for (int mt = 0; mt < 2; mt++)
                        #pragma unroll
                        for (int nt = 0; nt < 8; nt++)
                            mma16816(d[mt][nt], a[mt], bf[nt]);
                }
            }
        }
    }

    // ---- epilogue: fragments -> smem (reuse B region) -> coalesced global ----
    __syncthreads();
    float* accS = (float*)(smem + SM_B);
    #pragma unroll
    for (int mt = 0; mt < 2; mt++) {
        #pragma unroll
        for (int r = 0; r < 4; r++) {
            const int p = M0 + mt * 16 + (lane >> 2) + ((r >> 1) & 1) * 8;
            float* dst = accS + p * 72 + (lane & 3) * 2 + (r & 1);
            #pragma unroll
            for (int nt = 0; nt < 8; nt++)
                dst[nt * 8] = d[mt][nt][r];
        }
    }
    __syncthreads();
    {
        const size_t obase = ((size_t)(b * 64) * 256 + (size_t)(t1 * 16 + (tid >> 4))) * 256
                             + t2 * 16 + (tid & 15);
        const float* arow = accS + tid * 72;
        #pragma unroll 8
        for (int co = 0; co < 64; co++)
            out[obase + (size_t)co * 65536] = arow[co];
    }
}

extern "C" void kernel_launch(void* const* d_in, const int* in_sizes, int n_in,
                              void* d_out, int out_size) {
    const float* inp = (const float*)d_in[0];   // (8, 64, 256, 256) fp32
    const float* ker = (const float*)d_in[1];   // (9, 64, 64, 3, 3) fp32
    float* out = (float*)d_out;                 // (8, 64, 256, 256) fp32

    wtrans_kernel<<<(9 * 9 * 64 * 64 + 255) / 256, 256>>>(ker);

    cudaFuncSetAttribute(cocov_mma_kernel,
                         cudaFuncAttributeMaxDynamicSharedMemorySize, SM_TOTAL);
    dim3 grid(16, 16, 8);   // (t2, t1, b)
    cocov_mma_kernel<<<grid, 256, SM_TOTAL>>>(inp, out);
}

// round 6
// speedup vs baseline: 2.8453x; 1.0198x over previous
#include <cuda_runtime.h>
#include <cuda_bf16.h>
#include <cstdint>

// ============================================================================
// CoCov via mma.sync (HMMA) bf16x3, input-shift formulation + cp.async pipeline.
// out[p] = sum_{kt 3x3} sum_{tap 3x3} X_kt[p + (dh-1,dw-1)] @ W[kt,tap]
// A (input) pre-split to bf16 hi/lo swizzled panels in DRAM by asplit_kernel;
// B (weights) pre-split+swizzled by wtrans_kernel. Main kernel streams both
// with cp.async (4-slot B ring, double-buffered A), 3 precision passes in
// fp32 register fragments held across all 81 (kt,tap) combos.
// ============================================================================

// pre-swizzled weights: [T=kt*9+tap][prec hi/lo][ci 64][128B swizzled row]
__device__ __nv_bfloat16 g_bw[81 * 2 * 64 * 64];
// pre-split A panels: [b*256 + u1*16 + u2][prec 2][pix 256][128B swizzled row]
__device__ uint4 g_bA[2048 * 4096];

__global__ void wtrans_kernel(const float* __restrict__ K) {
    int gid = blockIdx.x * blockDim.x + threadIdx.x;
    if (gid >= 9 * 9 * 64 * 64) return;
    int co = gid & 63;
    int ci = (gid >> 6) & 63;
    int tp = (gid >> 12) % 9;
    int kt = (gid >> 12) / 9;
    float w = K[(((kt * 64 + co) * 64 + ci) * 9) + tp];   // [k][co][ci][dh][dw]
    __nv_bfloat16 hi = __float2bfloat16(w);
    __nv_bfloat16 lo = __float2bfloat16(w - __bfloat162float(hi));
    int T = kt * 9 + tp;
    // swizzled position within [ci][128B] plane (bf16 units)
    size_t base = (size_t)T * 8192 + ci * 64
                + (((co >> 3) ^ (ci & 7)) << 3) + (co & 7);
    g_bw[base]        = hi;
    g_bw[base + 4096] = lo;
}

__global__ void __launch_bounds__(256) asplit_kernel(const float* __restrict__ inp) {
    extern __shared__ char sm[];
    const int tid = threadIdx.x;
    const int u2 = blockIdx.x, u1 = blockIdx.y, b = blockIdx.z;
    const float* src = inp + (size_t)b * 64 * 65536
                     + (size_t)(u1 * 16 + (tid >> 4)) * 256 + u2 * 16 + (tid & 15);
    const uint32_t rowa = tid * 128;
    #pragma unroll
    for (int ch = 0; ch < 8; ch++) {
        uint32_t hi4[4], lo4[4];
        #pragma unroll
        for (int e = 0; e < 4; e++) {
            float x0 = __ldg(src + (size_t)(ch * 8 + 2 * e) * 65536);
            float x1 = __ldg(src + (size_t)(ch * 8 + 2 * e + 1) * 65536);
            __nv_bfloat16 h0 = __float2bfloat16(x0);
            __nv_bfloat16 h1 = __float2bfloat16(x1);
            __nv_bfloat16 l0 = __float2bfloat16(x0 - __bfloat162float(h0));
            __nv_bfloat16 l1 = __float2bfloat16(x1 - __bfloat162float(h1));
            __nv_bfloat162 hp(h0, h1), lp(l0, l1);
            hi4[e] = *(uint32_t*)&hp;
            lo4[e] = *(uint32_t*)&lp;
        }
        uint32_t off = rowa + ((ch ^ (tid & 7)) << 4);
        *(uint4*)(sm + off)         = make_uint4(hi4[0], hi4[1], hi4[2], hi4[3]);
        *(uint4*)(sm + 32768 + off) = make_uint4(lo4[0], lo4[1], lo4[2], lo4[3]);
    }
    __syncthreads();
    uint4* dst = g_bA + (size_t)(b * 256 + u1 * 16 + u2) * 4096;
    const uint4* s4 = (const uint4*)sm;
    #pragma unroll
    for (int k = 0; k < 16; k++) dst[tid + k * 256] = s4[tid + k * 256];
}

__device__ __forceinline__ uint32_t smem_u32(const void* p) {
    uint32_t a;
    asm("{ .reg .u64 t; cvta.to.shared.u64 t, %1; cvt.u32.u64 %0, t; }" : "=r"(a) : "l"(p));
    return a;
}
__device__ __forceinline__ void ldsm_x4(uint32_t* r, uint32_t addr) {
    asm volatile("ldmatrix.sync.aligned.m8n8.x4.shared.b16 {%0,%1,%2,%3}, [%4];"
                 : "=r"(r[0]), "=r"(r[1]), "=r"(r[2]), "=r"(r[3]) : "r"(addr));
}
__device__ __forceinline__ void ldsm_x4_t(uint32_t* r, uint32_t addr) {
    asm volatile("ldmatrix.sync.aligned.m8n8.x4.trans.shared.b16 {%0,%1,%2,%3}, [%4];"
                 : "=r"(r[0]), "=r"(r[1]), "=r"(r[2]), "=r"(r[3]) : "r"(addr));
}
__device__ __forceinline__ void mma16816(float* d, const uint32_t* a, const uint32_t* b) {
    asm volatile(
        "mma.sync.aligned.m16n8k16.row.col.f32.bf16.bf16.f32 "
        "{%0,%1,%2,%3}, {%4,%5,%6,%7}, {%8,%9}, {%0,%1,%2,%3};"
        : "+f"(d[0]), "+f"(d[1]), "+f"(d[2]), "+f"(d[3])
        : "r"(a[0]), "r"(a[1]), "r"(a[2]), "r"(a[3]), "r"(b[0]), "r"(b[1]));
}

#define CP16(dst, src, sz) \
    asm volatile("cp.async.cg.shared.global [%0], [%1], 16, %2;" \
                 :: "r"(dst), "l"(src), "r"(sz) : "memory")
#define CPCOMMIT() asm volatile("cp.async.commit_group;" ::: "memory")
#define CPWAIT2()  asm volatile("cp.async.wait_group 2;" ::: "memory")

// smem: A bufs: 2 x [prec 2][257 rows][128B] (row 256 = zeros), B ring: 4 x 16KB
#define A_PLANE  32896              // 257 * 128
#define ABUF_SZ  65792              // 2 * A_PLANE
#define SM_BR    131584             // 2 * ABUF_SZ
#define SM_TOTAL (131584 + 65536)

__global__ void __launch_bounds__(256, 1)
cocov_mma_kernel(float* __restrict__ out) {
    extern __shared__ char smem[];
    const uint32_t sb = smem_u32(smem);

    const int tid = threadIdx.x;
    const int lane = tid & 31;
    const int wid = tid >> 5;
    const int t2 = blockIdx.x, t1 = blockIdx.y, b = blockIdx.z;
    const int M0 = wid * 32;

    // zero rows (row 256 of each buf/prec plane), written once
    if (tid < 128) {
        int buf = tid >> 6, prec = (tid >> 5) & 1;
        *(float*)(smem + buf * ABUF_SZ + prec * A_PLANE + 256 * 128 + (tid & 31) * 4) = 0.f;
    }

    auto prefetch_B = [&](int T) {
        const char* src = (const char*)g_bw + (size_t)T * 16384;
        const uint32_t dst = sb + SM_BR + (T & 3) * 16384;
        #pragma unroll
        for (int it = 0; it < 4; it++) {
            int e = (tid + it * 256) * 16;
            CP16(dst + e, src + e, 16);
        }
    };
    auto prefetch_A = [&](int kt) {
        const int tt1 = t1 + kt / 3 - 1;
        const int tt2 = t2 + kt % 3 - 1;
        const bool v = ((unsigned)tt1 < 16u) && ((unsigned)tt2 < 16u);
        const uint4* srcp = g_bA + (size_t)(b * 256 + (v ? tt1 * 16 + tt2 : 0)) * 4096;
        const int sz = v ? 16 : 0;
        const uint32_t abase = sb + (kt & 1) * ABUF_SZ;
        #pragma unroll
        for (int it = 0; it < 16; it++) {
            int e = tid + it * 256;            // 0..4095
            int prec = e >> 11, rest = e & 2047;
            CP16(abase + prec * A_PLANE + rest * 16, (const char*)(srcp + e), sz);
        }
    };

    // ldmatrix lane addressing pieces
    const int a_kc_lane  = (lane >> 4);
    const int b_row_lane = (lane & 7) + ((lane >> 3) & 1) * 8;
    const int b_nc_lane  = (lane >> 4);
    const int jlane      = lane & 15;

    float d[2][8][4];
    #pragma unroll
    for (int mt = 0; mt < 2; mt++)
        #pragma unroll
        for (int nt = 0; nt < 8; nt++)
            #pragma unroll
            for (int r = 0; r < 4; r++) d[mt][nt][r] = 0.f;

    // prologue: prefetch taps 0..2 (+ A panel 0)
    prefetch_A(0); prefetch_B(0); CPCOMMIT();
    prefetch_B(1); CPCOMMIT();
    prefetch_B(2); CPCOMMIT();

    #pragma unroll 1
    for (int T = 0; T < 81; T++) {
        const int kt = T / 9, tp = T % 9;
        CPWAIT2();
        __syncthreads();
        const int Tn = T + 3;
        if (Tn <= 80) {
            prefetch_B(Tn);
            if (Tn % 9 == 0) prefetch_A(Tn / 9);
        }
        CPCOMMIT();

        const uint32_t abase = sb + (kt & 1) * ABUF_SZ;
        const uint32_t bbase = sb + SM_BR + (T & 3) * 16384;

        // shifted A row addresses for this tap (zero row 256 when invalid)
        const int dh = tp / 3 - 1, dw = tp % 3 - 1;
        const int sj = jlane + dw;
        const bool jv = (unsigned)sj < 16u;
        uint32_t rowbase[2];
        int key[2];
        #pragma unroll
        for (int mt = 0; mt < 2; mt++) {
            int si = wid * 2 + mt + dh;
            int srow = (jv && ((unsigned)si < 16u)) ? si * 16 + sj : 256;
            rowbase[mt] = abase + (uint32_t)srow * 128;
            key[mt] = srow & 7;
        }

        #pragma unroll
        for (int pass = 0; pass < 3; pass++) {
            const uint32_t pAoff = (pass == 1) ? (uint32_t)A_PLANE : 0u;
            const uint32_t pBoff = (pass == 2) ? 8192u : 0u;
            #pragma unroll
            for (int k16 = 0; k16 < 4; k16++) {
                const int kc = k16 * 2 + a_kc_lane;
                uint32_t a[2][4];
                #pragma unroll
                for (int mt = 0; mt < 2; mt++)
                    ldsm_x4(a[mt], rowbase[mt] + pAoff + ((kc ^ key[mt]) << 4));
                uint32_t bf[8][2];
                const int brow = k16 * 16 + b_row_lane;
                #pragma unroll
                for (int g = 0; g < 4; g++) {
                    int bnc = 2 * g + b_nc_lane;
                    uint32_t rr[4];
                    ldsm_x4_t(rr, bbase + pBoff + brow * 128
                                  + ((bnc ^ (brow & 7)) << 4));
                    bf[2 * g][0] = rr[0]; bf[2 * g][1] = rr[1];
                    bf[2 * g + 1][0] = rr[2]; bf[2 * g + 1][1] = rr[3];
                }
                #pragma unroll
                for (int mt = 0; mt < 2; mt++)
                    #pragma unroll
                    for (int nt = 0; nt < 8; nt++)
                        mma16816(d[mt][nt], a[mt], bf[nt]);
            }
        }
    }

    // ---- epilogue: fragments -> smem (reuse A region) -> coalesced global ----
    __syncthreads();
    float* accS = (float*)smem;
    #pragma unroll
    for (int mt = 0; mt < 2; mt++) {
        #pragma unroll
        for (int r = 0; r < 4; r++) {
            const int p = M0 + mt * 16 + (lane >> 2) + ((r >> 1) & 1) * 8;
            float* dst = accS + p * 72 + (lane & 3) * 2 + (r & 1);
            #pragma unroll
            for (int nt = 0; nt < 8; nt++)
                dst[nt * 8] = d[mt][nt][r];
        }
    }
    __syncthreads();
    {
        const size_t obase = ((size_t)(b * 64) * 256 + (size_t)(t1 * 16 + (tid >> 4))) * 256
                             + t2 * 16 + (tid & 15);
        const float* arow = accS + tid * 72;
        #pragma unroll 8
        for (int co = 0; co < 64; co++)
            out[obase + (size_t)co * 65536] = arow[co];
    }
}

extern "C" void kernel_launch(void* const* d_in, const int* in_sizes, int n_in,
                              void* d_out, int out_size) {
    const float* inp = (const float*)d_in[0];   // (8, 64, 256, 256) fp32
    const float* ker = (const float*)d_in[1];   // (9, 64, 64, 3, 3) fp32
    float* out = (float*)d_out;                 // (8, 64, 256, 256) fp32

    wtrans_kernel<<<(9 * 9 * 64 * 64 + 255) / 256, 256>>>(ker);

    cudaFuncSetAttribute(asplit_kernel,
                         cudaFuncAttributeMaxDynamicSharedMemorySize, 65536);
    dim3 grid(16, 16, 8);   // (u2/t2, u1/t1, b)
    asplit_kernel<<<grid, 256, 65536>>>(inp);

    cudaFuncSetAttribute(cocov_mma_kernel,
                         cudaFuncAttributeMaxDynamicSharedMemorySize, SM_TOTAL);
    cocov_mma_kernel<<<grid, 256, SM_TOTAL>>>(out);
}

// round 7
// speedup vs baseline: 4.3082x; 1.5141x over previous
#include <cuda_runtime.h>
#include <cuda_fp16.h>
#include <cstdint>

// ============================================================================
// CoCov via mma.sync (HMMA) fp16 2-pass, input-shift formulation + cp.async.
// out[p] = sum_{kt 3x3} sum_{tap 3x3} X_kt[p + (dh-1,dw-1)] @ W[kt,tap]
// x = xh + xl (two fp16, exact to 2^-22); w rounded once to fp16.
// passes: xh*w + xl*w, fp32 accumulate. B fragments shared across passes.
// ============================================================================

// pre-swizzled fp16 weights: [T=kt*9+tap][ci 64][128B swizzled row]
__device__ __half g_bw[81 * 64 * 64];
// pre-split A panels: [b*256 + u1*16 + u2][prec 2][pix 256][128B swizzled row]
__device__ uint4 g_bA[2048 * 4096];

__global__ void wtrans_kernel(const float* __restrict__ K) {
    int gid = blockIdx.x * blockDim.x + threadIdx.x;
    if (gid >= 81 * 64 * 64) return;
    int co = gid & 63;
    int ci = (gid >> 6) & 63;
    int T  = gid >> 12;
    int tp = T % 9, kt = T / 9;
    float w = K[(((kt * 64 + co) * 64 + ci) * 9) + tp];   // [k][co][ci][dh][dw]
    size_t base = (size_t)T * 4096 + ci * 64
                + (((co >> 3) ^ (ci & 7)) << 3) + (co & 7);
    g_bw[base] = __float2half(w);
}

__global__ void __launch_bounds__(256) asplit_kernel(const float* __restrict__ inp) {
    extern __shared__ char sm[];
    const int tid = threadIdx.x;
    const int u2 = blockIdx.x, u1 = blockIdx.y, b = blockIdx.z;
    const float* src = inp + (size_t)b * 64 * 65536
                     + (size_t)(u1 * 16 + (tid >> 4)) * 256 + u2 * 16 + (tid & 15);
    const uint32_t rowa = tid * 128;
    #pragma unroll
    for (int ch = 0; ch < 8; ch++) {
        uint32_t hi4[4], lo4[4];
        #pragma unroll
        for (int e = 0; e < 4; e++) {
            float x0 = __ldg(src + (size_t)(ch * 8 + 2 * e) * 65536);
            float x1 = __ldg(src + (size_t)(ch * 8 + 2 * e + 1) * 65536);
            __half h0 = __float2half(x0);
            __half h1 = __float2half(x1);
            __half l0 = __float2half(x0 - __half2float(h0));
            __half l1 = __float2half(x1 - __half2float(h1));
            __half2 hp(h0, h1), lp(l0, l1);
            hi4[e] = *(uint32_t*)&hp;
            lo4[e] = *(uint32_t*)&lp;
        }
        uint32_t off = rowa + ((ch ^ (tid & 7)) << 4);
        *(uint4*)(sm + off)         = make_uint4(hi4[0], hi4[1], hi4[2], hi4[3]);
        *(uint4*)(sm + 32768 + off) = make_uint4(lo4[0], lo4[1], lo4[2], lo4[3]);
    }
    __syncthreads();
    uint4* dst = g_bA + (size_t)(b * 256 + u1 * 16 + u2) * 4096;
    const uint4* s4 = (const uint4*)sm;
    #pragma unroll
    for (int k = 0; k < 16; k++) dst[tid + k * 256] = s4[tid + k * 256];
}

__device__ __forceinline__ uint32_t smem_u32(const void* p) {
    uint32_t a;
    asm("{ .reg .u64 t; cvta.to.shared.u64 t, %1; cvt.u32.u64 %0, t; }" : "=r"(a) : "l"(p));
    return a;
}
__device__ __forceinline__ void ldsm_x4(uint32_t* r, uint32_t addr) {
    asm volatile("ldmatrix.sync.aligned.m8n8.x4.shared.b16 {%0,%1,%2,%3}, [%4];"
                 : "=r"(r[0]), "=r"(r[1]), "=r"(r[2]), "=r"(r[3]) : "r"(addr));
}
__device__ __forceinline__ void ldsm_x4_t(uint32_t* r, uint32_t addr) {
    asm volatile("ldmatrix.sync.aligned.m8n8.x4.trans.shared.b16 {%0,%1,%2,%3}, [%4];"
                 : "=r"(r[0]), "=r"(r[1]), "=r"(r[2]), "=r"(r[3]) : "r"(addr));
}
__device__ __forceinline__ void mma16816(float* d, const uint32_t* a, const uint32_t* b) {
    asm volatile(
        "mma.sync.aligned.m16n8k16.row.col.f32.f16.f16.f32 "
        "{%0,%1,%2,%3}, {%4,%5,%6,%7}, {%8,%9}, {%0,%1,%2,%3};"
        : "+f"(d[0]), "+f"(d[1]), "+f"(d[2]), "+f"(d[3])
        : "r"(a[0]), "r"(a[1]), "r"(a[2]), "r"(a[3]), "r"(b[0]), "r"(b[1]));
}

#define CP16(dst, src, sz) \
    asm volatile("cp.async.cg.shared.global [%0], [%1], 16, %2;" \
                 :: "r"(dst), "l"(src), "r"(sz) : "memory")
#define CPCOMMIT() asm volatile("cp.async.commit_group;" ::: "memory")
#define CPWAIT2()  asm volatile("cp.async.wait_group 2;" ::: "memory")

// smem: A bufs: 2 x [prec 2][257 rows][128B] (row 256 = zeros), B ring: 4 x 8KB
#define A_PLANE  32896              // 257 * 128
#define ABUF_SZ  65792              // 2 * A_PLANE
#define SM_BR    131584             // 2 * ABUF_SZ
#define SM_TOTAL (131584 + 32768)

__global__ void __launch_bounds__(256, 1)
cocov_mma_kernel(float* __restrict__ out) {
    extern __shared__ char smem[];
    const uint32_t sb = smem_u32(smem);

    const int tid = threadIdx.x;
    const int lane = tid & 31;
    const int wid = tid >> 5;
    const int t2 = blockIdx.x, t1 = blockIdx.y, b = blockIdx.z;
    const int M0 = wid * 32;

    // zero rows (row 256 of each buf/prec plane), written once
    if (tid < 128) {
        int buf = tid >> 6, prec = (tid >> 5) & 1;
        *(float*)(smem + buf * ABUF_SZ + prec * A_PLANE + 256 * 128 + (tid & 31) * 4) = 0.f;
    }

    auto prefetch_B = [&](int T) {
        const char* src = (const char*)g_bw + (size_t)T * 8192;
        const uint32_t dst = sb + SM_BR + (T & 3) * 8192;
        #pragma unroll
        for (int it = 0; it < 2; it++) {
            int e = (tid + it * 256) * 16;
            CP16(dst + e, src + e, 16);
        }
    };
    auto prefetch_A = [&](int kt) {
        const int tt1 = t1 + kt / 3 - 1;
        const int tt2 = t2 + kt % 3 - 1;
        const bool v = ((unsigned)tt1 < 16u) && ((unsigned)tt2 < 16u);
        const uint4* srcp = g_bA + (size_t)(b * 256 + (v ? tt1 * 16 + tt2 : 0)) * 4096;
        const int sz = v ? 16 : 0;
        const uint32_t abase = sb + (kt & 1) * ABUF_SZ;
        #pragma unroll
        for (int it = 0; it < 16; it++) {
            int e = tid + it * 256;            // 0..4095
            int prec = e >> 11, rest = e & 2047;
            CP16(abase + prec * A_PLANE + rest * 16, (const char*)(srcp + e), sz);
        }
    };

    // ldmatrix lane addressing pieces
    const int a_kc_lane  = (lane >> 4);
    const int b_row_lane = (lane & 7) + ((lane >> 3) & 1) * 8;
    const int b_nc_lane  = (lane >> 4);
    const int jlane      = lane & 15;

    float d[2][8][4];
    #pragma unroll
    for (int mt = 0; mt < 2; mt++)
        #pragma unroll
        for (int nt = 0; nt < 8; nt++)
            #pragma unroll
            for (int r = 0; r < 4; r++) d[mt][nt][r] = 0.f;

    // prologue: prefetch taps 0..2 (+ A panel 0)
    prefetch_A(0); prefetch_B(0); CPCOMMIT();
    prefetch_B(1); CPCOMMIT();
    prefetch_B(2); CPCOMMIT();

    #pragma unroll 1
    for (int T = 0; T < 81; T++) {
        const int kt = T / 9, tp = T % 9;
        CPWAIT2();
        __syncthreads();
        const int Tn = T + 3;
        if (Tn <= 80) {
            prefetch_B(Tn);
            if (Tn % 9 == 0) prefetch_A(Tn / 9);
        }
        CPCOMMIT();

        const uint32_t abase = sb + (kt & 1) * ABUF_SZ;
        const uint32_t bbase = sb + SM_BR + (T & 3) * 8192;

        // shifted A row addresses for this tap (zero row 256 when invalid)
        const int dh = tp / 3 - 1, dw = tp % 3 - 1;
        const int sj = jlane + dw;
        const bool jv = (unsigned)sj < 16u;
        uint32_t rowbase[2];
        int key[2];
        #pragma unroll
        for (int mt = 0; mt < 2; mt++) {
            int si = wid * 2 + mt + dh;
            int srow = (jv && ((unsigned)si < 16u)) ? si * 16 + sj : 256;
            rowbase[mt] = abase + (uint32_t)srow * 128;
            key[mt] = srow & 7;
        }

        #pragma unroll
        for (int k16 = 0; k16 < 4; k16++) {
            // B fragments: loaded once, shared by both precision passes
            uint32_t bf[8][2];
            const int brow = k16 * 16 + b_row_lane;
            #pragma unroll
            for (int g = 0; g < 4; g++) {
                int bnc = 2 * g + b_nc_lane;
                uint32_t rr[4];
                ldsm_x4_t(rr, bbase + brow * 128 + ((bnc ^ (brow & 7)) << 4));
                bf[2 * g][0] = rr[0]; bf[2 * g][1] = rr[1];
                bf[2 * g + 1][0] = rr[2]; bf[2 * g + 1][1] = rr[3];
            }
            const int kc = k16 * 2 + a_kc_lane;
            #pragma unroll
            for (int pass = 0; pass < 2; pass++) {
                const uint32_t pAoff = pass ? (uint32_t)A_PLANE : 0u;
                uint32_t a[2][4];
                #pragma unroll
                for (int mt = 0; mt < 2; mt++)
                    ldsm_x4(a[mt], rowbase[mt] + pAoff + ((kc ^ key[mt]) << 4));
                #pragma unroll
                for (int mt = 0; mt < 2; mt++)
                    #pragma unroll
                    for (int nt = 0; nt < 8; nt++)
                        mma16816(d[mt][nt], a[mt], bf[nt]);
            }
        }
    }

    // ---- epilogue: fragments -> smem (reuse A region) -> coalesced global ----
    __syncthreads();
    float* accS = (float*)smem;
    #pragma unroll
    for (int mt = 0; mt < 2; mt++) {
        #pragma unroll
        for (int r = 0; r < 4; r++) {
            const int p = M0 + mt * 16 + (lane >> 2) + ((r >> 1) & 1) * 8;
            float* dst = accS + p * 72 + (lane & 3) * 2 + (r & 1);
            #pragma unroll
            for (int nt = 0; nt < 8; nt++)
                dst[nt * 8] = d[mt][nt][r];
        }
    }
    __syncthreads();
    {
        const size_t obase = ((size_t)(b * 64) * 256 + (size_t)(t1 * 16 + (tid >> 4))) * 256
                             + t2 * 16 + (tid & 15);
        const float* arow = accS + tid * 72;
        #pragma unroll 8
        for (int co = 0; co < 64; co++)
            out[obase + (size_t)co * 65536] = arow[co];
    }
}

extern "C" void kernel_launch(void* const* d_in, const int* in_sizes, int n_in,
                              void* d_out, int out_size) {
    const float* inp = (const float*)d_in[0];   // (8, 64, 256, 256) fp32
    const float* ker = (const float*)d_in[1];   // (9, 64, 64, 3, 3) fp32
    float* out = (float*)d_out;                 // (8, 64, 256, 256) fp32

    wtrans_kernel<<<(81 * 64 * 64 + 255) / 256, 256>>>(ker);

    cudaFuncSetAttribute(asplit_kernel,
                         cudaFuncAttributeMaxDynamicSharedMemorySize, 65536);
    dim3 grid(16, 16, 8);   // (u2/t2, u1/t1, b)
    asplit_kernel<<<grid, 256, 65536>>>(inp);

    cudaFuncSetAttribute(cocov_mma_kernel,
                         cudaFuncAttributeMaxDynamicSharedMemorySize, SM_TOTAL);
    cocov_mma_kernel<<<grid, 256, SM_TOTAL>>>(out);
}

// round 8
// speedup vs baseline: 6.9744x; 1.6189x over previous
#include <cuda_runtime.h>
#include <cuda_fp16.h>
#include <cstdint>

// ============================================================================
// CoCov via mma.sync (HMMA) fp16 single-pass, input-shift formulation + cp.async.
// out[p] = sum_{kt 3x3} sum_{tap 3x3} X_kt[p + (dh-1,dw-1)] @ W[kt,tap]
// x and w each rounded once to fp16; fp32 accumulate (error ~3e-4 << 1e-3).
// A pre-converted to swizzled fp16 panels in DRAM; B pre-swizzled fp16.
// ============================================================================

// pre-swizzled fp16 weights: [T=kt*9+tap][ci 64][128B swizzled row]
__device__ __half g_bw[81 * 64 * 64];
// pre-converted A panels: [b*256 + u1*16 + u2][pix 256][128B swizzled row]
__device__ uint4 g_bA[2048 * 2048];

__global__ void wtrans_kernel(const float* __restrict__ K) {
    int gid = blockIdx.x * blockDim.x + threadIdx.x;
    if (gid >= 81 * 64 * 64) return;
    int co = gid & 63;
    int ci = (gid >> 6) & 63;
    int T  = gid >> 12;
    int tp = T % 9, kt = T / 9;
    float w = K[(((kt * 64 + co) * 64 + ci) * 9) + tp];   // [k][co][ci][dh][dw]
    size_t base = (size_t)T * 4096 + ci * 64
                + (((co >> 3) ^ (ci & 7)) << 3) + (co & 7);
    g_bw[base] = __float2half(w);
}

__global__ void __launch_bounds__(256) asplit_kernel(const float* __restrict__ inp) {
    extern __shared__ char sm[];
    const int tid = threadIdx.x;
    const int u2 = blockIdx.x, u1 = blockIdx.y, b = blockIdx.z;
    const float* src = inp + (size_t)b * 64 * 65536
                     + (size_t)(u1 * 16 + (tid >> 4)) * 256 + u2 * 16 + (tid & 15);
    const uint32_t rowa = tid * 128;
    #pragma unroll
    for (int ch = 0; ch < 8; ch++) {
        uint32_t hi4[4];
        #pragma unroll
        for (int e = 0; e < 4; e++) {
            float x0 = __ldg(src + (size_t)(ch * 8 + 2 * e) * 65536);
            float x1 = __ldg(src + (size_t)(ch * 8 + 2 * e + 1) * 65536);
            __half2 hp(__float2half(x0), __float2half(x1));
            hi4[e] = *(uint32_t*)&hp;
        }
        uint32_t off = rowa + ((ch ^ (tid & 7)) << 4);
        *(uint4*)(sm + off) = make_uint4(hi4[0], hi4[1], hi4[2], hi4[3]);
    }
    __syncthreads();
    uint4* dst = g_bA + (size_t)(b * 256 + u1 * 16 + u2) * 2048;
    const uint4* s4 = (const uint4*)sm;
    #pragma unroll
    for (int k = 0; k < 8; k++) dst[tid + k * 256] = s4[tid + k * 256];
}

__device__ __forceinline__ uint32_t smem_u32(const void* p) {
    uint32_t a;
    asm("{ .reg .u64 t; cvta.to.shared.u64 t, %1; cvt.u32.u64 %0, t; }" : "=r"(a) : "l"(p));
    return a;
}
__device__ __forceinline__ void ldsm_x4(uint32_t* r, uint32_t addr) {
    asm volatile("ldmatrix.sync.aligned.m8n8.x4.shared.b16 {%0,%1,%2,%3}, [%4];"
                 : "=r"(r[0]), "=r"(r[1]), "=r"(r[2]), "=r"(r[3]) : "r"(addr));
}
__device__ __forceinline__ void ldsm_x4_t(uint32_t* r, uint32_t addr) {
    asm volatile("ldmatrix.sync.aligned.m8n8.x4.trans.shared.b16 {%0,%1,%2,%3}, [%4];"
                 : "=r"(r[0]), "=r"(r[1]), "=r"(r[2]), "=r"(r[3]) : "r"(addr));
}
__device__ __forceinline__ void mma16816(float* d, const uint32_t* a, const uint32_t* b) {
    asm volatile(
        "mma.sync.aligned.m16n8k16.row.col.f32.f16.f16.f32 "
        "{%0,%1,%2,%3}, {%4,%5,%6,%7}, {%8,%9}, {%0,%1,%2,%3};"
        : "+f"(d[0]), "+f"(d[1]), "+f"(d[2]), "+f"(d[3])
        : "r"(a[0]), "r"(a[1]), "r"(a[2]), "r"(a[3]), "r"(b[0]), "r"(b[1]));
}

#define CP16(dst, src, sz) \
    asm volatile("cp.async.cg.shared.global [%0], [%1], 16, %2;" \
                 :: "r"(dst), "l"(src), "r"(sz) : "memory")
#define CPCOMMIT() asm volatile("cp.async.commit_group;" ::: "memory")
#define CPWAIT2()  asm volatile("cp.async.wait_group 2;" ::: "memory")

// smem: A bufs: 2 x [257 rows][128B] (row 256 = zeros), B ring: 4 x 8KB
#define ABUF_SZ  32896              // 257 * 128
#define SM_BR    65792              // 2 * ABUF_SZ
#define SM_TOTAL (65792 + 32768)

__global__ void __launch_bounds__(256, 1)
cocov_mma_kernel(float* __restrict__ out) {
    extern __shared__ char smem[];
    const uint32_t sb = smem_u32(smem);

    const int tid = threadIdx.x;
    const int lane = tid & 31;
    const int wid = tid >> 5;
    const int t2 = blockIdx.x, t1 = blockIdx.y, b = blockIdx.z;
    const int M0 = wid * 32;

    // zero rows (row 256 of each A buf), written once
    if (tid < 64) {
        int buf = tid >> 5;
        *(float*)(smem + buf * ABUF_SZ + 256 * 128 + (tid & 31) * 4) = 0.f;
    }

    auto prefetch_B = [&](int T) {
        const char* src = (const char*)g_bw + (size_t)T * 8192;
        const uint32_t dst = sb + SM_BR + (T & 3) * 8192;
        #pragma unroll
        for (int it = 0; it < 2; it++) {
            int e = (tid + it * 256) * 16;
            CP16(dst + e, src + e, 16);
        }
    };
    auto prefetch_A = [&](int kt) {
        const int tt1 = t1 + kt / 3 - 1;
        const int tt2 = t2 + kt % 3 - 1;
        const bool v = ((unsigned)tt1 < 16u) && ((unsigned)tt2 < 16u);
        const uint4* srcp = g_bA + (size_t)(b * 256 + (v ? tt1 * 16 + tt2 : 0)) * 2048;
        const int sz = v ? 16 : 0;
        const uint32_t abase = sb + (kt & 1) * ABUF_SZ;
        #pragma unroll
        for (int it = 0; it < 8; it++) {
            int e = tid + it * 256;            // 0..2047
            CP16(abase + e * 16, (const char*)(srcp + e), sz);
        }
    };

    // ldmatrix lane addressing pieces
    const int a_kc_lane  = (lane >> 4);
    const int b_row_lane = (lane & 7) + ((lane >> 3) & 1) * 8;
    const int b_nc_lane  = (lane >> 4);
    const int jlane      = lane & 15;

    float d[2][8][4];
    #pragma unroll
    for (int mt = 0; mt < 2; mt++)
        #pragma unroll
        for (int nt = 0; nt < 8; nt++)
            #pragma unroll
            for (int r = 0; r < 4; r++) d[mt][nt][r] = 0.f;

    // prologue: prefetch taps 0..2 (+ A panel 0)
    prefetch_A(0); prefetch_B(0); CPCOMMIT();
    prefetch_B(1); CPCOMMIT();
    prefetch_B(2); CPCOMMIT();

    #pragma unroll 1
    for (int T = 0; T < 81; T++) {
        const int kt = T / 9, tp = T % 9;
        CPWAIT2();
        __syncthreads();
        const int Tn = T + 3;
        if (Tn <= 80) {
            prefetch_B(Tn);
            if (Tn % 9 == 0) prefetch_A(Tn / 9);
        }
        CPCOMMIT();

        const uint32_t abase = sb + (kt & 1) * ABUF_SZ;
        const uint32_t bbase = sb + SM_BR + (T & 3) * 8192;

        // shifted A row addresses for this tap (zero row 256 when invalid)
        const int dh = tp / 3 - 1, dw = tp % 3 - 1;
        const int sj = jlane + dw;
        const bool jv = (unsigned)sj < 16u;
        uint32_t rowbase[2];
        int key[2];
        #pragma unroll
        for (int mt = 0; mt < 2; mt++) {
            int si = wid * 2 + mt + dh;
            int srow = (jv && ((unsigned)si < 16u)) ? si * 16 + sj : 256;
            rowbase[mt] = abase + (uint32_t)srow * 128;
            key[mt] = srow & 7;
        }

        #pragma unroll
        for (int k16 = 0; k16 < 4; k16++) {
            uint32_t bf[8][2];
            const int brow = k16 * 16 + b_row_lane;
            #pragma unroll
            for (int g = 0; g < 4; g++) {
                int bnc = 2 * g + b_nc_lane;
                uint32_t rr[4];
                ldsm_x4_t(rr, bbase + brow * 128 + ((bnc ^ (brow & 7)) << 4));
                bf[2 * g][0] = rr[0]; bf[2 * g][1] = rr[1];
                bf[2 * g + 1][0] = rr[2]; bf[2 * g + 1][1] = rr[3];
            }
            const int kc = k16 * 2 + a_kc_lane;
            uint32_t a[2][4];
            #pragma unroll
            for (int mt = 0; mt < 2; mt++)
                ldsm_x4(a[mt], rowbase[mt] + ((kc ^ key[mt]) << 4));
            #pragma unroll
            for (int mt = 0; mt < 2; mt++)
                #pragma unroll
                for (int nt = 0; nt < 8; nt++)
                    mma16816(d[mt][nt], a[mt], bf[nt]);
        }
    }

    // ---- epilogue: fragments -> smem (reuse A region) -> coalesced global ----
    __syncthreads();
    float* accS = (float*)smem;
    #pragma unroll
    for (int mt = 0; mt < 2; mt++) {
        #pragma unroll
        for (int r = 0; r < 4; r++) {
            const int p = M0 + mt * 16 + (lane >> 2) + ((r >> 1) & 1) * 8;
            float* dst = accS + p * 72 + (lane & 3) * 2 + (r & 1);
            #pragma unroll
            for (int nt = 0; nt < 8; nt++)
                dst[nt * 8] = d[mt][nt][r];
        }
    }
    __syncthreads();
    {
        const size_t obase = ((size_t)(b * 64) * 256 + (size_t)(t1 * 16 + (tid >> 4))) * 256
                             + t2 * 16 + (tid & 15);
        const float* arow = accS + tid * 72;
        #pragma unroll 8
        for (int co = 0; co < 64; co++)
            out[obase + (size_t)co * 65536] = arow[co];
    }
}

extern "C" void kernel_launch(void* const* d_in, const int* in_sizes, int n_in,
                              void* d_out, int out_size) {
    const float* inp = (const float*)d_in[0];   // (8, 64, 256, 256) fp32
    const float* ker = (const float*)d_in[1];   // (9, 64, 64, 3, 3) fp32
    float* out = (float*)d_out;                 // (8, 64, 256, 256) fp32

    wtrans_kernel<<<(81 * 64 * 64 + 255) / 256, 256>>>(ker);

    cudaFuncSetAttribute(asplit_kernel,
                         cudaFuncAttributeMaxDynamicSharedMemorySize, 32768);
    dim3 grid(16, 16, 8);   // (u2/t2, u1/t1, b)
    asplit_kernel<<<grid, 256, 32768>>>(inp);

    cudaFuncSetAttribute(cocov_mma_kernel,
                         cudaFuncAttributeMaxDynamicSharedMemorySize, SM_TOTAL);
    cocov_mma_kernel<<<grid, 256, SM_TOTAL>>>(out);
}

// round 9
// speedup vs baseline: 8.4659x; 1.2139x over previous
#include <cuda_runtime.h>
#include <cuda_fp16.h>
#include <cstdint>

// ============================================================================
// CoCov via mma.sync (HMMA) fp16 single-pass, input-shift formulation.
// out[p] = sum_{kt 3x3} sum_{tap 3x3} X_kt[p + (dh-1,dw-1)] @ W[kt,tap]
// 128-thread CTAs (4 warps x 64 pixels), 2 CTAs/SM for barrier decoupling.
// A pre-converted to swizzled fp16 panels in DRAM; B pre-swizzled fp16.
// ============================================================================

// pre-swizzled fp16 weights: [T=kt*9+tap][ci 64][128B swizzled row]
__device__ __half g_bw[81 * 64 * 64];
// pre-converted A panels: [b*256 + u1*16 + u2][pix 256][128B swizzled row]
__device__ uint4 g_bA[2048 * 2048];

__global__ void wtrans_kernel(const float* __restrict__ K) {
    int gid = blockIdx.x * blockDim.x + threadIdx.x;
    if (gid >= 81 * 64 * 64) return;
    int co = gid & 63;
    int ci = (gid >> 6) & 63;
    int T  = gid >> 12;
    int tp = T % 9, kt = T / 9;
    float w = K[(((kt * 64 + co) * 64 + ci) * 9) + tp];   // [k][co][ci][dh][dw]
    size_t base = (size_t)T * 4096 + ci * 64
                + (((co >> 3) ^ (ci & 7)) << 3) + (co & 7);
    g_bw[base] = __float2half(w);
}

__global__ void __launch_bounds__(256) asplit_kernel(const float* __restrict__ inp) {
    extern __shared__ char sm[];
    const int tid = threadIdx.x;
    const int u2 = blockIdx.x, u1 = blockIdx.y, b = blockIdx.z;
    const float* src = inp + (size_t)b * 64 * 65536
                     + (size_t)(u1 * 16 + (tid >> 4)) * 256 + u2 * 16 + (tid & 15);
    const uint32_t rowa = tid * 128;
    #pragma unroll
    for (int ch = 0; ch < 8; ch++) {
        uint32_t hi4[4];
        #pragma unroll
        for (int e = 0; e < 4; e++) {
            float x0 = __ldg(src + (size_t)(ch * 8 + 2 * e) * 65536);
            float x1 = __ldg(src + (size_t)(ch * 8 + 2 * e + 1) * 65536);
            __half2 hp(__float2half(x0), __float2half(x1));
            hi4[e] = *(uint32_t*)&hp;
        }
        uint32_t off = rowa + ((ch ^ (tid & 7)) << 4);
        *(uint4*)(sm + off) = make_uint4(hi4[0], hi4[1], hi4[2], hi4[3]);
    }
    __syncthreads();
    uint4* dst = g_bA + (size_t)(b * 256 + u1 * 16 + u2) * 2048;
    const uint4* s4 = (const uint4*)sm;
    #pragma unroll
    for (int k = 0; k < 8; k++) dst[tid + k * 256] = s4[tid + k * 256];
}

__device__ __forceinline__ uint32_t smem_u32(const void* p) {
    uint32_t a;
    asm("{ .reg .u64 t; cvta.to.shared.u64 t, %1; cvt.u32.u64 %0, t; }" : "=r"(a) : "l"(p));
    return a;
}
__device__ __forceinline__ void ldsm_x4(uint32_t* r, uint32_t addr) {
    asm volatile("ldmatrix.sync.aligned.m8n8.x4.shared.b16 {%0,%1,%2,%3}, [%4];"
                 : "=r"(r[0]), "=r"(r[1]), "=r"(r[2]), "=r"(r[3]) : "r"(addr));
}
__device__ __forceinline__ void ldsm_x4_t(uint32_t* r, uint32_t addr) {
    asm volatile("ldmatrix.sync.aligned.m8n8.x4.trans.shared.b16 {%0,%1,%2,%3}, [%4];"
                 : "=r"(r[0]), "=r"(r[1]), "=r"(r[2]), "=r"(r[3]) : "r"(addr));
}
__device__ __forceinline__ void mma16816(float* d, const uint32_t* a, const uint32_t* b) {
    asm volatile(
        "mma.sync.aligned.m16n8k16.row.col.f32.f16.f16.f32 "
        "{%0,%1,%2,%3}, {%4,%5,%6,%7}, {%8,%9}, {%0,%1,%2,%3};"
        : "+f"(d[0]), "+f"(d[1]), "+f"(d[2]), "+f"(d[3])
        : "r"(a[0]), "r"(a[1]), "r"(a[2]), "r"(a[3]), "r"(b[0]), "r"(b[1]));
}

#define CP16(dst, src, sz) \
    asm volatile("cp.async.cg.shared.global [%0], [%1], 16, %2;" \
                 :: "r"(dst), "l"(src), "r"(sz) : "memory")
#define CPCOMMIT() asm volatile("cp.async.commit_group;" ::: "memory")
#define CPWAIT2()  asm volatile("cp.async.wait_group 2;" ::: "memory")

// smem: A bufs: 2 x [257 rows][128B] (row 256 = zeros), B ring: 4 x 8KB
#define ABUF_SZ  32896              // 257 * 128
#define SM_BR    65792              // 2 * ABUF_SZ
#define SM_TOTAL (65792 + 32768)    // 98560 -> 2 CTAs/SM

__global__ void __launch_bounds__(128, 2)
cocov_mma_kernel(float* __restrict__ out) {
    extern __shared__ char smem[];
    const uint32_t sb = smem_u32(smem);

    const int tid = threadIdx.x;
    const int lane = tid & 31;
    const int wid = tid >> 5;              // 0..3, each warp: 64 pixels
    const int t2 = blockIdx.x, t1 = blockIdx.y, b = blockIdx.z;
    const int M0 = wid * 64;

    // zero rows (row 256 of each A buf), written once
    if (tid < 64) {
        int buf = tid >> 5;
        *(float*)(smem + buf * ABUF_SZ + 256 * 128 + (tid & 31) * 4) = 0.f;
    }

    auto prefetch_B = [&](int T) {
        const char* src = (const char*)g_bw + (size_t)T * 8192;
        const uint32_t dst = sb + SM_BR + (T & 3) * 8192;
        #pragma unroll
        for (int it = 0; it < 4; it++) {
            int e = (tid + it * 128) * 16;
            CP16(dst + e, src + e, 16);
        }
    };
    auto prefetch_A = [&](int kt) {
        const int tt1 = t1 + kt / 3 - 1;
        const int tt2 = t2 + kt % 3 - 1;
        const bool v = ((unsigned)tt1 < 16u) && ((unsigned)tt2 < 16u);
        const uint4* srcp = g_bA + (size_t)(b * 256 + (v ? tt1 * 16 + tt2 : 0)) * 2048;
        const int sz = v ? 16 : 0;
        const uint32_t abase = sb + (kt & 1) * ABUF_SZ;
        #pragma unroll
        for (int it = 0; it < 16; it++) {
            int e = tid + it * 128;            // 0..2047
            CP16(abase + e * 16, (const char*)(srcp + e), sz);
        }
    };

    // ldmatrix lane addressing pieces
    const int a_kc_lane  = (lane >> 4);
    const int b_row_lane = (lane & 7) + ((lane >> 3) & 1) * 8;
    const int b_nc_lane  = (lane >> 4);
    const int jlane      = lane & 15;

    float d[4][8][4];
    #pragma unroll
    for (int mt = 0; mt < 4; mt++)
        #pragma unroll
        for (int nt = 0; nt < 8; nt++)
            #pragma unroll
            for (int r = 0; r < 4; r++) d[mt][nt][r] = 0.f;

    // prologue: prefetch taps 0..2 (+ A panel 0)
    prefetch_A(0); prefetch_B(0); CPCOMMIT();
    prefetch_B(1); CPCOMMIT();
    prefetch_B(2); CPCOMMIT();

    #pragma unroll 1
    for (int T = 0; T < 81; T++) {
        const int kt = T / 9, tp = T % 9;
        CPWAIT2();
        __syncthreads();
        const int Tn = T + 3;
        if (Tn <= 80) {
            prefetch_B(Tn);
            if (Tn % 9 == 0) prefetch_A(Tn / 9);
        }
        CPCOMMIT();

        const uint32_t abase = sb + (kt & 1) * ABUF_SZ;
        const uint32_t bbase = sb + SM_BR + (T & 3) * 8192;

        // shifted A row addresses for this tap (zero row 256 when invalid)
        const int dh = tp / 3 - 1, dw = tp % 3 - 1;
        const int sj = jlane + dw;
        const bool jv = (unsigned)sj < 16u;
        uint32_t rowbase[4];
        int key[4];
        #pragma unroll
        for (int mt = 0; mt < 4; mt++) {
            int si = wid * 4 + mt + dh;
            int srow = (jv && ((unsigned)si < 16u)) ? si * 16 + sj : 256;
            rowbase[mt] = abase + (uint32_t)srow * 128;
            key[mt] = srow & 7;
        }

        #pragma unroll
        for (int k16 = 0; k16 < 4; k16++) {
            // B fragments: loaded once per k16, shared by all 4 m-tiles
            uint32_t bf[8][2];
            const int brow = k16 * 16 + b_row_lane;
            #pragma unroll
            for (int g = 0; g < 4; g++) {
                int bnc = 2 * g + b_nc_lane;
                uint32_t rr[4];
                ldsm_x4_t(rr, bbase + brow * 128 + ((bnc ^ (brow & 7)) << 4));
                bf[2 * g][0] = rr[0]; bf[2 * g][1] = rr[1];
                bf[2 * g + 1][0] = rr[2]; bf[2 * g + 1][1] = rr[3];
            }
            const int kc = k16 * 2 + a_kc_lane;
            #pragma unroll
            for (int mt = 0; mt < 4; mt++) {
                uint32_t a[4];
                ldsm_x4(a, rowbase[mt] + ((kc ^ key[mt]) << 4));
                #pragma unroll
                for (int nt = 0; nt < 8; nt++)
                    mma16816(d[mt][nt], a, bf[nt]);
            }
        }
    }

    // ---- epilogue: fragments -> smem (reuse A region) -> coalesced global ----
    __syncthreads();
    float* accS = (float*)smem;
    #pragma unroll
    for (int mt = 0; mt < 4; mt++) {
        #pragma unroll
        for (int r = 0; r < 4; r++) {
            const int p = M0 + mt * 16 + (lane >> 2) + ((r >> 1) & 1) * 8;
            float* dst = accS + p * 72 + (lane & 3) * 2 + (r & 1);
            #pragma unroll
            for (int nt = 0; nt < 8; nt++)
                dst[nt * 8] = d[mt][nt][r];
        }
    }
    __syncthreads();
    {
        #pragma unroll
        for (int h = 0; h < 2; h++) {
            const int p = tid + h * 128;
            const size_t obase = ((size_t)(b * 64) * 256
                                  + (size_t)(t1 * 16 + (p >> 4))) * 256
                                 + t2 * 16 + (p & 15);
            const float* arow = accS + p * 72;
            #pragma unroll 8
            for (int co = 0; co < 64; co++)
                out[obase + (size_t)co * 65536] = arow[co];
        }
    }
}

extern "C" void kernel_launch(void* const* d_in, const int* in_sizes, int n_in,
                              void* d_out, int out_size) {
    const float* inp = (const float*)d_in[0];   // (8, 64, 256, 256) fp32
    const float* ker = (const float*)d_in[1];   // (9, 64, 64, 3, 3) fp32
    float* out = (float*)d_out;                 // (8, 64, 256, 256) fp32

    wtrans_kernel<<<(81 * 64 * 64 + 255) / 256, 256>>>(ker);

    cudaFuncSetAttribute(asplit_kernel,
                         cudaFuncAttributeMaxDynamicSharedMemorySize, 32768);
    dim3 grid(16, 16, 8);   // (u2/t2, u1/t1, b)
    asplit_kernel<<<grid, 256, 32768>>>(inp);

    cudaFuncSetAttribute(cocov_mma_kernel,
                         cudaFuncAttributeMaxDynamicSharedMemorySize, SM_TOTAL);
    cocov_mma_kernel<<<grid, 128, SM_TOTAL>>>(out);
}